// round 16
// baseline (speedup 1.0000x reference)
#include <cuda_runtime.h>
#include <cuda_fp16.h>
#include <cstdint>

#define S_TOK   8192
#define DMODEL  2048
#define DFF     8192
#define NEXP    8
#define CAP     2560   // ceil(1.25 * 8192*2 / 8)

// ---------------- scratch (static device globals; no runtime alloc) ----------------
__device__ __half g_H[(size_t)NEXP * CAP * DFF];         // relu(x@w1), half
__device__ __half g_Eout[(size_t)NEXP * CAP * DMODEL];   // expert output per slot, half
__device__ __half g_w1t[(size_t)NEXP * DFF * DMODEL];    // w1^T half: [E][DFF][DMODEL]
__device__ __half g_w2t[(size_t)NEXP * DMODEL * DFF];    // w2^T half: [E][DMODEL][DFF]
__device__ __half g_xh[(size_t)S_TOK * DMODEL];          // x, half
__device__ int    g_disp_tok[NEXP * CAP];
__device__ int    g_slot[S_TOK * 2];
__device__ float  g_wt[S_TOK * 2];
__device__ int    g_topk_idx[S_TOK * 2];
__device__ float  g_topk_gate[S_TOK * 2];

// ---------------- PTX helpers -------------------------------------------------------
__device__ __forceinline__ void cp_async16(uint32_t smem, const void* gmem) {
    asm volatile("cp.async.cg.shared.global [%0], [%1], 16;\n" :: "r"(smem), "l"(gmem));
}
__device__ __forceinline__ void cp_commit() {
    asm volatile("cp.async.commit_group;\n" ::);
}
template <int N>
__device__ __forceinline__ void cp_wait() {
    asm volatile("cp.async.wait_group %0;\n" :: "n"(N));
}
__device__ __forceinline__ void mma_f16(float d[4], const uint32_t a[4], const uint32_t b[2]) {
    asm volatile(
        "mma.sync.aligned.m16n8k16.row.col.f32.f16.f16.f32 "
        "{%0,%1,%2,%3}, {%4,%5,%6,%7}, {%8,%9}, {%0,%1,%2,%3};\n"
        : "+f"(d[0]), "+f"(d[1]), "+f"(d[2]), "+f"(d[3])
        : "r"(a[0]), "r"(a[1]), "r"(a[2]), "r"(a[3]), "r"(b[0]), "r"(b[1]));
}

// ---------------- pre-passes: fp32 -> fp16 ------------------------------------------
__global__ void cvt_xh(const float* __restrict__ in, __half* __restrict__ out, int n4) {
    int i = blockIdx.x * blockDim.x + threadIdx.x;
    int stride = gridDim.x * blockDim.x;
    const float4* I = (const float4*)in;
    __half2* O = (__half2*)out;
    for (; i < n4; i += stride) {
        float4 v = I[i];
        O[i * 2 + 0] = __floats2half2_rn(v.x, v.y);
        O[i * 2 + 1] = __floats2half2_rn(v.z, v.w);
    }
}

// in fp32 [E][K][N] -> out half [E][N][K]
__global__ void transpose_h(const float* __restrict__ in, __half* __restrict__ out,
                            int K, int N) {
    __shared__ float tileT[32][132];
    const int e  = blockIdx.z;
    const float* I = in  + (size_t)e * K * N;
    __half*      O = out + (size_t)e * K * N;
    const int n0 = blockIdx.x * 32, k0 = blockIdx.y * 128;
    const int tid = threadIdx.x;

#pragma unroll
    for (int idx = tid; idx < 1024; idx += 256) {
        const int r  = idx >> 3;
        const int c4 = idx & 7;
        float4 v = *(const float4*)(I + (size_t)(k0 + r) * N + n0 + c4 * 4);
        tileT[c4 * 4 + 0][r] = v.x;
        tileT[c4 * 4 + 1][r] = v.y;
        tileT[c4 * 4 + 2][r] = v.z;
        tileT[c4 * 4 + 3][r] = v.w;
    }
    __syncthreads();

#pragma unroll
    for (int idx = tid; idx < 512; idx += 256) {
        const int j = idx >> 4;
        const int u = idx & 15;
        const float* src = &tileT[j][u * 8];
        __half2 h[4];
        h[0] = __floats2half2_rn(src[0], src[1]);
        h[1] = __floats2half2_rn(src[2], src[3]);
        h[2] = __floats2half2_rn(src[4], src[5]);
        h[3] = __floats2half2_rn(src[6], src[7]);
        *(uint4*)(O + (size_t)(n0 + j) * K + k0 + u * 8) = *(uint4*)h;
    }
}

// ---------------- 1) gating: logits -> softmax -> top-2 (one warp per token) -------
__global__ void gate_kernel(const float* __restrict__ x, const float* __restrict__ Wg) {
    int gw   = (blockIdx.x * blockDim.x + threadIdx.x) >> 5;
    int lane = threadIdx.x & 31;
    if (gw >= S_TOK) return;
    const float* xr = x + (size_t)gw * DMODEL;

    float acc[NEXP];
#pragma unroll
    for (int e = 0; e < NEXP; e++) acc[e] = 0.f;

    for (int d = lane; d < DMODEL; d += 32) {
        float xv = xr[d];
        float4 wa = *(const float4*)(Wg + (size_t)d * NEXP);
        float4 wb = *(const float4*)(Wg + (size_t)d * NEXP + 4);
        acc[0] = fmaf(xv, wa.x, acc[0]);
        acc[1] = fmaf(xv, wa.y, acc[1]);
        acc[2] = fmaf(xv, wa.z, acc[2]);
        acc[3] = fmaf(xv, wa.w, acc[3]);
        acc[4] = fmaf(xv, wb.x, acc[4]);
        acc[5] = fmaf(xv, wb.y, acc[5]);
        acc[6] = fmaf(xv, wb.z, acc[6]);
        acc[7] = fmaf(xv, wb.w, acc[7]);
    }
#pragma unroll
    for (int off = 16; off; off >>= 1)
#pragma unroll
        for (int e = 0; e < NEXP; e++)
            acc[e] += __shfl_xor_sync(0xffffffffu, acc[e], off);
    if (lane == 0) {
        float mx = acc[0];
#pragma unroll
        for (int e = 1; e < NEXP; e++) mx = fmaxf(mx, acc[e]);
        float p[NEXP], den = 0.f;
#pragma unroll
        for (int e = 0; e < NEXP; e++) { p[e] = expf(acc[e] - mx); den += p[e]; }
        float inv = 1.0f / den;

        int i0 = 0; float v0 = p[0];
#pragma unroll
        for (int e = 1; e < NEXP; e++) if (p[e] > v0) { v0 = p[e]; i0 = e; }
        int i1 = (i0 == 0) ? 1 : 0; float v1 = p[i1];
#pragma unroll
        for (int e = 0; e < NEXP; e++)
            if (e != i0 && p[e] > v1) { v1 = p[e]; i1 = e; }

        g_topk_idx[gw * 2 + 0]  = i0;
        g_topk_idx[gw * 2 + 1]  = i1;
        g_topk_gate[gw * 2 + 0] = v0 * inv;
        g_topk_gate[gw * 2 + 1] = v1 * inv;
    }
}

// ---------------- 2) routing: ordered per-expert cumsum + capacity ------------------
__global__ void route_kernel() {
    __shared__ int counts[512][NEXP];
    const int t = threadIdx.x;
    for (int i = t; i < NEXP * CAP; i += 512) g_disp_tok[i] = 0;

    int base = t * 32;
    int cnt[NEXP];
#pragma unroll
    for (int e = 0; e < NEXP; e++) cnt[e] = 0;
    int eidx[32];
#pragma unroll
    for (int i = 0; i < 32; i++) {
        eidx[i] = g_topk_idx[base + i];
        cnt[eidx[i]]++;
    }
#pragma unroll
    for (int e = 0; e < NEXP; e++) counts[t][e] = cnt[e];
    __syncthreads();
    if (t < NEXP) {
        int run = 0;
        for (int i = 0; i < 512; i++) {
            int v = counts[i][t];
            counts[i][t] = run;
            run += v;
        }
    }
    __syncthreads();
    int run[NEXP];
#pragma unroll
    for (int e = 0; e < NEXP; e++) run[e] = counts[t][e];
#pragma unroll
    for (int i = 0; i < 32; i++) {
        int idx = base + i;
        int e   = eidx[i];
        int pos = run[e]++;
        if (pos < CAP) {
            g_disp_tok[e * CAP + pos] = idx >> 1;
            g_slot[idx] = e * CAP + pos;
            g_wt[idx]   = g_topk_gate[idx];
        } else {
            g_slot[idx] = -1;
            g_wt[idx]   = 0.f;
        }
    }
}

// ---------------- 3+4) FP16 tensor-core GEMM (round-9 champion config) --------------
// OUT_MODE: 0 = half + relu (gemm1), 1 = half, no relu (gemm2)
template <int KD, bool GATHER, int OUT_MODE>
__global__ __launch_bounds__(256, 2)
void gemm_h(const __half* __restrict__ Abase, const __half* __restrict__ Bbase,
            __half* __restrict__ Cbase, const int N) {
    constexpr int BM = 128, BK = 16, NST = 6;
    constexpr int RSTR = 24;
    constexpr int TSZ  = BM * RSTR;
    constexpr int STG  = 2 * TSZ;

    extern __shared__ __half sm[];
    __shared__ int stoks[BM];

    const int e  = blockIdx.z;
    const int m0 = blockIdx.y * BM;
    const int n0 = blockIdx.x * 128;

    const int tid  = threadIdx.x;
    const int lane = tid & 31, wid = tid >> 5;
    const int gid  = lane >> 2, t4 = lane & 3;
    const int warpM = wid >> 2, warpN = wid & 3;

    if (GATHER) {
        if (tid < BM) stoks[tid] = g_disp_tok[e * CAP + m0 + tid];
        __syncthreads();
    }

    const int row = tid >> 1;
    const int ch  = (tid & 1) * 8;
    const __half* aptr;
    if (GATHER) aptr = Abase + (size_t)stoks[row] * KD + ch;
    else        aptr = Abase + ((size_t)e * CAP + m0 + row) * KD + ch;
    const __half* bptr = Bbase + ((size_t)e * N + n0 + row) * KD + ch;

    const uint32_t sbase = (uint32_t)__cvta_generic_to_shared(sm);
    const uint32_t dA = sbase + (row * RSTR + ch) * 2;
    const uint32_t dB = dA + TSZ * 2;

    float d[4][4][4];
#pragma unroll
    for (int i = 0; i < 4; i++)
#pragma unroll
        for (int j = 0; j < 4; j++)
#pragma unroll
            for (int r = 0; r < 4; r++) d[i][j][r] = 0.f;

    constexpr int KT = KD / BK;

    auto issue = [&](int kt) {
        const uint32_t so = (uint32_t)((kt % NST) * STG * 2);
        const size_t ko = (size_t)kt * BK;
        cp_async16(dA + so, aptr + ko);
        cp_async16(dB + so, bptr + ko);
        cp_commit();
    };

    auto kstep = [&](int s) {
        const uint32_t* as = (const uint32_t*)(sm + (s % NST) * STG);
        const uint32_t* bs = as + TSZ / 2;
        uint32_t af[4][4], bf[4][2];
#pragma unroll
        for (int i = 0; i < 4; i++) {
            const int m = warpM * 64 + i * 16 + gid;
            const uint32_t* a = as + m * 12 + t4;
            af[i][0] = a[0];
            af[i][1] = a[8 * 12];
            af[i][2] = a[4];
            af[i][3] = a[8 * 12 + 4];
        }
#pragma unroll
        for (int j = 0; j < 4; j++) {
            const int n = warpN * 32 + j * 8 + gid;
            const uint32_t* b = bs + n * 12 + t4;
            bf[j][0] = b[0];
            bf[j][1] = b[4];
        }
#pragma unroll
        for (int i = 0; i < 4; i++)
#pragma unroll
            for (int j = 0; j < 4; j++)
                mma_f16(d[i][j], af[i], bf[j]);
    };

    issue(0); issue(1); issue(2); issue(3);

#pragma unroll 1
    for (int kt = 0; kt < KT; kt += 2) {
        if (kt + 4 <= KT) cp_wait<2>(); else cp_wait<0>();
        __syncthreads();

        kstep(kt);
        if (kt + 4 < KT) issue(kt + 4);
        kstep(kt + 1);
        if (kt + 5 < KT) issue(kt + 5);
    }

    // epilogue: half output (relu for gemm1)
    __half* C = Cbase + ((size_t)e * CAP + m0) * N + n0;
#pragma unroll
    for (int i = 0; i < 4; i++) {
        const int mrow = warpM * 64 + i * 16 + gid;
#pragma unroll
        for (int j = 0; j < 4; j++) {
            const int ncol = warpN * 32 + j * 8 + t4 * 2;
            float v0 = d[i][j][0], v1 = d[i][j][1];
            float v2 = d[i][j][2], v3 = d[i][j][3];
            if (OUT_MODE == 0) {
                v0 = fmaxf(v0, 0.f); v1 = fmaxf(v1, 0.f);
                v2 = fmaxf(v2, 0.f); v3 = fmaxf(v3, 0.f);
            }
            *(__half2*)(C + (size_t)mrow * N + ncol)       = __floats2half2_rn(v0, v1);
            *(__half2*)(C + (size_t)(mrow + 8) * N + ncol) = __floats2half2_rn(v2, v3);
        }
    }
}

// ---------------- 5) combine: out[s,:] = sum_j w_j * Eout[slot_j,:] (half in) -------
__global__ void combine_kernel(float* __restrict__ out) {
    const int s = blockIdx.x;
    const int sl0 = g_slot[s * 2 + 0];
    const int sl1 = g_slot[s * 2 + 1];
    const float w0 = g_wt[s * 2 + 0];
    const float w1 = g_wt[s * 2 + 1];

    const uint2* e0 = (sl0 >= 0) ? (const uint2*)(g_Eout + (size_t)sl0 * DMODEL) : nullptr;
    const uint2* e1 = (sl1 >= 0) ? (const uint2*)(g_Eout + (size_t)sl1 * DMODEL) : nullptr;
    float4* dst = (float4*)(out + (size_t)s * DMODEL);

    for (int m = threadIdx.x; m < DMODEL / 4; m += blockDim.x) {
        float4 r = make_float4(0.f, 0.f, 0.f, 0.f);
        if (e0) {
            uint2 u = e0[m];
            float2 a = __half22float2(*(__half2*)&u.x);
            float2 b = __half22float2(*(__half2*)&u.y);
            r.x = fmaf(w0, a.x, r.x); r.y = fmaf(w0, a.y, r.y);
            r.z = fmaf(w0, b.x, r.z); r.w = fmaf(w0, b.y, r.w);
        }
        if (e1) {
            uint2 u = e1[m];
            float2 a = __half22float2(*(__half2*)&u.x);
            float2 b = __half22float2(*(__half2*)&u.y);
            r.x = fmaf(w1, a.x, r.x); r.y = fmaf(w1, a.y, r.y);
            r.z = fmaf(w1, b.x, r.z); r.w = fmaf(w1, b.y, r.w);
        }
        dst[m] = r;
    }
}

// ---------------- launch: pure serial (champion order) ------------------------------
extern "C" void kernel_launch(void* const* d_in, const int* in_sizes, int n_in,
                              void* d_out, int out_size) {
    const float* x  = (const float*)d_in[0];
    const float* Wg = (const float*)d_in[1];
    const float* w1 = (const float*)d_in[2];
    const float* w2 = (const float*)d_in[3];
    float* out = (float*)d_out;

    __half *Hp, *Ep, *W1t, *W2t, *Xh;
    cudaGetSymbolAddress((void**)&Hp,  g_H);
    cudaGetSymbolAddress((void**)&Ep,  g_Eout);
    cudaGetSymbolAddress((void**)&W1t, g_w1t);
    cudaGetSymbolAddress((void**)&W2t, g_w2t);
    cudaGetSymbolAddress((void**)&Xh,  g_xh);

    const int dynsz = 6 * 12288;   // 73728 B per CTA (2 CTAs/SM = 144 KB)
    cudaFuncSetAttribute(gemm_h<DMODEL, true,  0>,
                         cudaFuncAttributeMaxDynamicSharedMemorySize, dynsz);
    cudaFuncSetAttribute(gemm_h<DFF,    false, 1>,
                         cudaFuncAttributeMaxDynamicSharedMemorySize, dynsz);

    gate_kernel<<<(S_TOK * 32 + 255) / 256, 256>>>(x, Wg);
    route_kernel<<<1, 512>>>();

    cvt_xh<<<592, 256>>>(x, Xh, S_TOK * DMODEL / 4);
    transpose_h<<<dim3(DFF / 32, DMODEL / 128, NEXP), 256>>>(w1, W1t, DMODEL, DFF);
    transpose_h<<<dim3(DMODEL / 32, DFF / 128, NEXP), 256>>>(w2, W2t, DFF, DMODEL);

    // GEMM1: H = relu(xh @ w1)
    dim3 g1(DFF / 128, CAP / 128, NEXP);     // (64, 20, 8)
    gemm_h<DMODEL, true, 0><<<g1, 256, dynsz>>>(Xh, W1t, Hp, DFF);

    // GEMM2: Eout = H @ w2 (half output)
    dim3 g2(DMODEL / 128, CAP / 128, NEXP);  // (16, 20, 8)
    gemm_h<DFF, false, 1><<<g2, 256, dynsz>>>(Hp, W2t, Ep, DMODEL);

    combine_kernel<<<S_TOK, 128>>>(out);
}

// round 17
// speedup vs baseline: 1.7595x; 1.7595x over previous
#include <cuda_runtime.h>
#include <cuda_fp16.h>
#include <cstdint>

#define S_TOK   8192
#define DMODEL  2048
#define DFF     8192
#define NEXP    8
#define CAP     2560   // ceil(1.25 * 8192*2 / 8)

// ---------------- scratch (static device globals; no runtime alloc) ----------------
__device__ __half g_H[(size_t)NEXP * CAP * DFF];         // relu(x@w1), half
__device__ float  g_Eout[(size_t)NEXP * CAP * DMODEL];   // expert output per slot
__device__ __half g_w1t[(size_t)NEXP * DFF * DMODEL];    // w1^T half: [E][DFF][DMODEL]
__device__ __half g_w2t[(size_t)NEXP * DMODEL * DFF];    // w2^T half: [E][DMODEL][DFF]
__device__ __half g_xh[(size_t)S_TOK * DMODEL];          // x, half
__device__ int    g_disp_tok[NEXP * CAP];
__device__ int    g_expert_cnt[NEXP];                    // used slots per expert (<=CAP)
__device__ int    g_slot[S_TOK * 2];
__device__ float  g_wt[S_TOK * 2];
__device__ int    g_topk_idx[S_TOK * 2];
__device__ float  g_topk_gate[S_TOK * 2];

// ---------------- PTX helpers -------------------------------------------------------
__device__ __forceinline__ void cp_async16(uint32_t smem, const void* gmem) {
    asm volatile("cp.async.cg.shared.global [%0], [%1], 16;\n" :: "r"(smem), "l"(gmem));
}
__device__ __forceinline__ void cp_commit() {
    asm volatile("cp.async.commit_group;\n" ::);
}
template <int N>
__device__ __forceinline__ void cp_wait() {
    asm volatile("cp.async.wait_group %0;\n" :: "n"(N));
}
__device__ __forceinline__ void mma_f16(float d[4], const uint32_t a[4], const uint32_t b[2]) {
    asm volatile(
        "mma.sync.aligned.m16n8k16.row.col.f32.f16.f16.f32 "
        "{%0,%1,%2,%3}, {%4,%5,%6,%7}, {%8,%9}, {%0,%1,%2,%3};\n"
        : "+f"(d[0]), "+f"(d[1]), "+f"(d[2]), "+f"(d[3])
        : "r"(a[0]), "r"(a[1]), "r"(a[2]), "r"(a[3]), "r"(b[0]), "r"(b[1]));
}

// ---------------- pre-passes: fp32 -> fp16 ------------------------------------------
__global__ void cvt_xh(const float* __restrict__ in, __half* __restrict__ out, int n4) {
    int i = blockIdx.x * blockDim.x + threadIdx.x;
    int stride = gridDim.x * blockDim.x;
    const float4* I = (const float4*)in;
    __half2* O = (__half2*)out;
    for (; i < n4; i += stride) {
        float4 v = I[i];
        O[i * 2 + 0] = __floats2half2_rn(v.x, v.y);
        O[i * 2 + 1] = __floats2half2_rn(v.z, v.w);
    }
}

// in fp32 [E][K][N] -> out half [E][N][K]
__global__ void transpose_h(const float* __restrict__ in, __half* __restrict__ out,
                            int K, int N) {
    __shared__ float tileT[32][132];
    const int e  = blockIdx.z;
    const float* I = in  + (size_t)e * K * N;
    __half*      O = out + (size_t)e * K * N;
    const int n0 = blockIdx.x * 32, k0 = blockIdx.y * 128;
    const int tid = threadIdx.x;

#pragma unroll
    for (int idx = tid; idx < 1024; idx += 256) {
        const int r  = idx >> 3;
        const int c4 = idx & 7;
        float4 v = *(const float4*)(I + (size_t)(k0 + r) * N + n0 + c4 * 4);
        tileT[c4 * 4 + 0][r] = v.x;
        tileT[c4 * 4 + 1][r] = v.y;
        tileT[c4 * 4 + 2][r] = v.z;
        tileT[c4 * 4 + 3][r] = v.w;
    }
    __syncthreads();

#pragma unroll
    for (int idx = tid; idx < 512; idx += 256) {
        const int j = idx >> 4;
        const int u = idx & 15;
        const float* src = &tileT[j][u * 8];
        __half2 h[4];
        h[0] = __floats2half2_rn(src[0], src[1]);
        h[1] = __floats2half2_rn(src[2], src[3]);
        h[2] = __floats2half2_rn(src[4], src[5]);
        h[3] = __floats2half2_rn(src[6], src[7]);
        *(uint4*)(O + (size_t)(n0 + j) * K + k0 + u * 8) = *(uint4*)h;
    }
}

// ---------------- 1) gating: logits -> softmax -> top-2 (one warp per token) -------
__global__ void gate_kernel(const float* __restrict__ x, const float* __restrict__ Wg) {
    int gw   = (blockIdx.x * blockDim.x + threadIdx.x) >> 5;
    int lane = threadIdx.x & 31;
    if (gw >= S_TOK) return;
    const float* xr = x + (size_t)gw * DMODEL;

    float acc[NEXP];
#pragma unroll
    for (int e = 0; e < NEXP; e++) acc[e] = 0.f;

    for (int d = lane; d < DMODEL; d += 32) {
        float xv = xr[d];
        float4 wa = *(const float4*)(Wg + (size_t)d * NEXP);
        float4 wb = *(const float4*)(Wg + (size_t)d * NEXP + 4);
        acc[0] = fmaf(xv, wa.x, acc[0]);
        acc[1] = fmaf(xv, wa.y, acc[1]);
        acc[2] = fmaf(xv, wa.z, acc[2]);
        acc[3] = fmaf(xv, wa.w, acc[3]);
        acc[4] = fmaf(xv, wb.x, acc[4]);
        acc[5] = fmaf(xv, wb.y, acc[5]);
        acc[6] = fmaf(xv, wb.z, acc[6]);
        acc[7] = fmaf(xv, wb.w, acc[7]);
    }
#pragma unroll
    for (int off = 16; off; off >>= 1)
#pragma unroll
        for (int e = 0; e < NEXP; e++)
            acc[e] += __shfl_xor_sync(0xffffffffu, acc[e], off);
    if (lane == 0) {
        float mx = acc[0];
#pragma unroll
        for (int e = 1; e < NEXP; e++) mx = fmaxf(mx, acc[e]);
        float p[NEXP], den = 0.f;
#pragma unroll
        for (int e = 0; e < NEXP; e++) { p[e] = expf(acc[e] - mx); den += p[e]; }
        float inv = 1.0f / den;

        int i0 = 0; float v0 = p[0];
#pragma unroll
        for (int e = 1; e < NEXP; e++) if (p[e] > v0) { v0 = p[e]; i0 = e; }
        int i1 = (i0 == 0) ? 1 : 0; float v1 = p[i1];
#pragma unroll
        for (int e = 0; e < NEXP; e++)
            if (e != i0 && p[e] > v1) { v1 = p[e]; i1 = e; }

        g_topk_idx[gw * 2 + 0]  = i0;
        g_topk_idx[gw * 2 + 1]  = i1;
        g_topk_gate[gw * 2 + 0] = v0 * inv;
        g_topk_gate[gw * 2 + 1] = v1 * inv;
    }
}

// ---------------- 2) routing: ordered per-expert cumsum + capacity ------------------
__global__ void route_kernel() {
    __shared__ int counts[512][NEXP];
    const int t = threadIdx.x;
    for (int i = t; i < NEXP * CAP; i += 512) g_disp_tok[i] = 0;

    int base = t * 32;
    int cnt[NEXP];
#pragma unroll
    for (int e = 0; e < NEXP; e++) cnt[e] = 0;
    int eidx[32];
#pragma unroll
    for (int i = 0; i < 32; i++) {
        eidx[i] = g_topk_idx[base + i];
        cnt[eidx[i]]++;
    }
#pragma unroll
    for (int e = 0; e < NEXP; e++) counts[t][e] = cnt[e];
    __syncthreads();
    if (t < NEXP) {
        int run = 0;
        for (int i = 0; i < 512; i++) {
            int v = counts[i][t];
            counts[i][t] = run;
            run += v;
        }
        // total assignments for this expert, capped at capacity -> GEMM tile bound
        g_expert_cnt[t] = run < CAP ? run : CAP;
    }
    __syncthreads();
    int run[NEXP];
#pragma unroll
    for (int e = 0; e < NEXP; e++) run[e] = counts[t][e];
#pragma unroll
    for (int i = 0; i < 32; i++) {
        int idx = base + i;
        int e   = eidx[i];
        int pos = run[e]++;
        if (pos < CAP) {
            g_disp_tok[e * CAP + pos] = idx >> 1;
            g_slot[idx] = e * CAP + pos;
            g_wt[idx]   = g_topk_gate[idx];
        } else {
            g_slot[idx] = -1;
            g_wt[idx]   = 0.f;
        }
    }
}

// ---------------- 3+4) FP16 tensor-core GEMM (champion config + tile skip) ----------
// C[e,m,n] = A[e,m,:] @ B^T[e,n,:]   (A [rows][KD] half, B [E][N][KD] half, k-major)
// 128x128 block tile, BK=16 stages, 6-stage cp.async ring, one barrier per two
// stages, 8 warps (2x4, 64x32 warp tiles), 2 CTAs/SM. CTAs whose M-tile lies
// entirely beyond the expert's used slot count early-exit (slack never read).
template <int KD, bool GATHER, bool HALF_RELU_OUT>
__global__ __launch_bounds__(256, 2)
void gemm_h(const __half* __restrict__ Abase, const __half* __restrict__ Bbase,
            void* __restrict__ Cbase, const int N) {
    constexpr int BM = 128, BK = 16, NST = 6;
    constexpr int RSTR = 24;
    constexpr int TSZ  = BM * RSTR;
    constexpr int STG  = 2 * TSZ;

    extern __shared__ __half sm[];
    __shared__ int stoks[BM];

    const int e  = blockIdx.z;
    const int m0 = blockIdx.y * BM;
    const int n0 = blockIdx.x * 128;

    // skip tiles entirely in the capacity-slack region (unwritten/unread)
    if (m0 >= g_expert_cnt[e]) return;

    const int tid  = threadIdx.x;
    const int lane = tid & 31, wid = tid >> 5;
    const int gid  = lane >> 2, t4 = lane & 3;
    const int warpM = wid >> 2, warpN = wid & 3;

    if (GATHER) {
        if (tid < BM) stoks[tid] = g_disp_tok[e * CAP + m0 + tid];
        __syncthreads();
    }

    const int row = tid >> 1;
    const int ch  = (tid & 1) * 8;
    const __half* aptr;
    if (GATHER) aptr = Abase + (size_t)stoks[row] * KD + ch;
    else        aptr = Abase + ((size_t)e * CAP + m0 + row) * KD + ch;
    const __half* bptr = Bbase + ((size_t)e * N + n0 + row) * KD + ch;

    const uint32_t sbase = (uint32_t)__cvta_generic_to_shared(sm);
    const uint32_t dA = sbase + (row * RSTR + ch) * 2;
    const uint32_t dB = dA + TSZ * 2;

    float d[4][4][4];
#pragma unroll
    for (int i = 0; i < 4; i++)
#pragma unroll
        for (int j = 0; j < 4; j++)
#pragma unroll
            for (int r = 0; r < 4; r++) d[i][j][r] = 0.f;

    constexpr int KT = KD / BK;

    auto issue = [&](int kt) {
        const uint32_t so = (uint32_t)((kt % NST) * STG * 2);
        const size_t ko = (size_t)kt * BK;
        cp_async16(dA + so, aptr + ko);
        cp_async16(dB + so, bptr + ko);
        cp_commit();
    };

    auto kstep = [&](int s) {
        const uint32_t* as = (const uint32_t*)(sm + (s % NST) * STG);
        const uint32_t* bs = as + TSZ / 2;
        uint32_t af[4][4], bf[4][2];
#pragma unroll
        for (int i = 0; i < 4; i++) {
            const int m = warpM * 64 + i * 16 + gid;
            const uint32_t* a = as + m * 12 + t4;
            af[i][0] = a[0];
            af[i][1] = a[8 * 12];
            af[i][2] = a[4];
            af[i][3] = a[8 * 12 + 4];
        }
#pragma unroll
        for (int j = 0; j < 4; j++) {
            const int n = warpN * 32 + j * 8 + gid;
            const uint32_t* b = bs + n * 12 + t4;
            bf[j][0] = b[0];
            bf[j][1] = b[4];
        }
#pragma unroll
        for (int i = 0; i < 4; i++)
#pragma unroll
            for (int j = 0; j < 4; j++)
                mma_f16(d[i][j], af[i], bf[j]);
    };

    issue(0); issue(1); issue(2); issue(3);

#pragma unroll 1
    for (int kt = 0; kt < KT; kt += 2) {
        if (kt + 4 <= KT) cp_wait<2>(); else cp_wait<0>();
        __syncthreads();

        kstep(kt);
        if (kt + 4 < KT) issue(kt + 4);
        kstep(kt + 1);
        if (kt + 5 < KT) issue(kt + 5);
    }

    if (HALF_RELU_OUT) {
        __half* C = (__half*)Cbase + ((size_t)e * CAP + m0) * N + n0;
#pragma unroll
        for (int i = 0; i < 4; i++) {
            const int mrow = warpM * 64 + i * 16 + gid;
#pragma unroll
            for (int j = 0; j < 4; j++) {
                const int ncol = warpN * 32 + j * 8 + t4 * 2;
                __half2 h0 = __floats2half2_rn(fmaxf(d[i][j][0], 0.f), fmaxf(d[i][j][1], 0.f));
                __half2 h1 = __floats2half2_rn(fmaxf(d[i][j][2], 0.f), fmaxf(d[i][j][3], 0.f));
                *(__half2*)(C + (size_t)mrow * N + ncol)       = h0;
                *(__half2*)(C + (size_t)(mrow + 8) * N + ncol) = h1;
            }
        }
    } else {
        float* C = (float*)Cbase + ((size_t)e * CAP + m0) * N + n0;
#pragma unroll
        for (int i = 0; i < 4; i++) {
            const int mrow = warpM * 64 + i * 16 + gid;
#pragma unroll
            for (int j = 0; j < 4; j++) {
                const int ncol = warpN * 32 + j * 8 + t4 * 2;
                *(float2*)(C + (size_t)mrow * N + ncol)       = make_float2(d[i][j][0], d[i][j][1]);
                *(float2*)(C + (size_t)(mrow + 8) * N + ncol) = make_float2(d[i][j][2], d[i][j][3]);
            }
        }
    }
}

// ---------------- 5) combine: out[s,:] = sum_j w_j * Eout[slot_j,:] -----------------
__global__ void combine_kernel(float* __restrict__ out) {
    const int s = blockIdx.x;
    const int sl0 = g_slot[s * 2 + 0];
    const int sl1 = g_slot[s * 2 + 1];
    const float w0 = g_wt[s * 2 + 0];
    const float w1 = g_wt[s * 2 + 1];

    const float4* e0 = (sl0 >= 0) ? (const float4*)(g_Eout + (size_t)sl0 * DMODEL) : nullptr;
    const float4* e1 = (sl1 >= 0) ? (const float4*)(g_Eout + (size_t)sl1 * DMODEL) : nullptr;
    float4* dst = (float4*)(out + (size_t)s * DMODEL);

    for (int m = threadIdx.x; m < DMODEL / 4; m += blockDim.x) {
        float4 r = make_float4(0.f, 0.f, 0.f, 0.f);
        if (e0) {
            float4 v = e0[m];
            r.x = fmaf(w0, v.x, r.x); r.y = fmaf(w0, v.y, r.y);
            r.z = fmaf(w0, v.z, r.z); r.w = fmaf(w0, v.w, r.w);
        }
        if (e1) {
            float4 v = e1[m];
            r.x = fmaf(w1, v.x, r.x); r.y = fmaf(w1, v.y, r.y);
            r.z = fmaf(w1, v.z, r.z); r.w = fmaf(w1, v.w, r.w);
        }
        dst[m] = r;
    }
}

// ---------------- launch: pure serial (champion order) ------------------------------
extern "C" void kernel_launch(void* const* d_in, const int* in_sizes, int n_in,
                              void* d_out, int out_size) {
    const float* x  = (const float*)d_in[0];
    const float* Wg = (const float*)d_in[1];
    const float* w1 = (const float*)d_in[2];
    const float* w2 = (const float*)d_in[3];
    float* out = (float*)d_out;

    __half *Hp, *W1t, *W2t, *Xh;
    float *Ep;
    cudaGetSymbolAddress((void**)&Hp,  g_H);
    cudaGetSymbolAddress((void**)&Ep,  g_Eout);
    cudaGetSymbolAddress((void**)&W1t, g_w1t);
    cudaGetSymbolAddress((void**)&W2t, g_w2t);
    cudaGetSymbolAddress((void**)&Xh,  g_xh);

    const int dynsz = 6 * 12288;   // 73728 B per CTA (2 CTAs/SM = 144 KB)
    cudaFuncSetAttribute(gemm_h<DMODEL, true,  true >,
                         cudaFuncAttributeMaxDynamicSharedMemorySize, dynsz);
    cudaFuncSetAttribute(gemm_h<DFF,    false, false>,
                         cudaFuncAttributeMaxDynamicSharedMemorySize, dynsz);

    gate_kernel<<<(S_TOK * 32 + 255) / 256, 256>>>(x, Wg);
    route_kernel<<<1, 512>>>();

    cvt_xh<<<592, 256>>>(x, Xh, S_TOK * DMODEL / 4);
    transpose_h<<<dim3(DFF / 32, DMODEL / 128, NEXP), 256>>>(w1, W1t, DMODEL, DFF);
    transpose_h<<<dim3(DMODEL / 32, DFF / 128, NEXP), 256>>>(w2, W2t, DFF, DMODEL);

    // GEMM1: H = relu(xh @ w1)
    dim3 g1(DFF / 128, CAP / 128, NEXP);     // (64, 20, 8)
    gemm_h<DMODEL, true, true><<<g1, 256, dynsz>>>(Xh, W1t, Hp, DFF);

    // GEMM2: Eout = H @ w2
    dim3 g2(DMODEL / 128, CAP / 128, NEXP);  // (16, 20, 8)
    gemm_h<DFF, false, false><<<g2, 256, dynsz>>>(Hp, W2t, Ep, DMODEL);

    combine_kernel<<<S_TOK, 128>>>(out);
}